// round 9
// baseline (speedup 1.0000x reference)
#include <cuda_runtime.h>
#include <cstdint>
#include <cstddef>

#define HDIM   128
#define GDIM   512      // 4*H
#define BATCH  256
#define SEQ    512
#define DIN    80
#define EMB    256
#define KREGP  28       // k-pairs register-resident per column (k in [0,56))
#define KSP    36       // k-pairs per column in shared memory (k in [56,128))
#define WSTRIDE 38      // float2 row stride: 304B = 48 mod 128 -> conflict-free LDS.128
#define NSEG   4
#define TSEG   128      // steps per lstm segment launch
#define LOG2E  1.4426950408889634f
#define C2LOG2E 2.8853900817779268f

typedef unsigned long long u64;

// ---------------- device scratch (no allocations allowed) ----------------
__device__ float g_G[(size_t)BATCH * SEQ * GDIM];    // gate pre-activations (input part, prescaled)
__device__ float g_hout[(size_t)BATCH * SEQ * HDIM]; // per-step h_out
__device__ float g_Wc[GDIM * DIN];                   // fused + prescaled  W_ih @ W_in
__device__ float g_bc[GDIM];                         // fused + prescaled  bias
__device__ float2 g_WTrp[KREGP * GDIM];              // reg-weight pairs: [p][j] (prescaled)
__device__ float2 g_WTp[GDIM * KSP];                 // smem-weight pairs: [j][p-KREGP] (prescaled)
// LSTM state carried between segment launches
__device__ float g_hst[BATCH * HDIM];
__device__ float g_cst[BATCH * HDIM];
__device__ float g_hsA[BATCH * HDIM];
__device__ float g_hsB[BATCH * HDIM];
__device__ float g_csA[BATCH * HDIM];
__device__ float g_csB[BATCH * HDIM];

// ---------------- f32x2 helpers ----------------
__device__ __forceinline__ void fma2(u64& d, u64 a, u64 b) {
    asm("fma.rn.f32x2 %0, %1, %2, %0;" : "+l"(d) : "l"(a), "l"(b));
}
__device__ __forceinline__ u64 pack2(float lo, float hi) {
    u64 r; asm("mov.b64 %0, {%1, %2};" : "=l"(r) : "f"(lo), "f"(hi)); return r;
}
__device__ __forceinline__ u64 dup2(float x) {
    u64 r; asm("mov.b64 %0, {%1, %1};" : "=l"(r) : "f"(x)); return r;
}
__device__ __forceinline__ float2 unpack2(u64 v) {
    float2 r; asm("mov.b64 {%0, %1}, %2;" : "=f"(r.x), "=f"(r.y) : "l"(v)); return r;
}

// ---------------- fast activation primitives (inputs prescaled by log2e) ----------------
__device__ __forceinline__ float ex2f(float x) {
    float r; asm("ex2.approx.f32 %0, %1;" : "=f"(r) : "f"(x)); return r;
}
__device__ __forceinline__ float rcpf(float x) {
    float r; asm("rcp.approx.f32 %0, %1;" : "=f"(r) : "f"(x)); return r;
}
__device__ __forceinline__ float sig_p(float g)  { return rcpf(1.0f + ex2f(-g)); }
__device__ __forceinline__ float tanh_p(float g) { return fmaf(-2.0f, rcpf(ex2f(g) + 1.0f), 1.0f); }

// ---------------- kernel 0: fold W_in into W_ih, prescale, pack W_hh^T ----------------
__global__ void combine_kernel(const float* __restrict__ W_in, const float* __restrict__ b_in,
                               const float* __restrict__ W_ih, const float* __restrict__ b_ih,
                               const float* __restrict__ W_hh, const float* __restrict__ b_hh) {
    __shared__ float wih[EMB];
    int j = blockIdx.x;           // 0..511
    int tid = threadIdx.x;        // 128 threads (= k index)
    float s = ((j >> 7) == 2) ? C2LOG2E : LOG2E;   // g-gate rows get 2*log2e
    for (int e = tid; e < EMB; e += 128) wih[e] = W_ih[j * EMB + e];
    if (!(tid & 1)) {
        float2 wp = make_float2(s * W_hh[j * HDIM + tid], s * W_hh[j * HDIM + tid + 1]);
        int p = tid >> 1;
        if (p < KREGP) g_WTrp[p * GDIM + j] = wp;           // register part
        else           g_WTp[j * KSP + (p - KREGP)] = wp;   // smem part
    }
    __syncthreads();
    if (tid < DIN) {
        float acc = 0.f;
        #pragma unroll 8
        for (int e = 0; e < EMB; e++) acc = fmaf(wih[e], W_in[e * DIN + tid], acc);
        g_Wc[j * DIN + tid] = s * acc;
    }
    if (tid == 96) {
        float acc = b_ih[j] + b_hh[j];
        #pragma unroll 8
        for (int e = 0; e < EMB; e++) acc = fmaf(wih[e], b_in[e], acc);
        g_bc[j] = s * acc;
    }
}

// ---------------- kernel 1: G[m][j] = x[m][:] . Wc[j][:] + bc[j] ----------------
__global__ void __launch_bounds__(256, 2) gemm_kernel(const float* __restrict__ x) {
    __shared__ float As[40][132];
    __shared__ float Bs[40][132];
    __shared__ float bcs[128];

    int tid = threadIdx.x;
    int n0 = blockIdx.x * 128;
    int m0 = blockIdx.y * 128;
    if (tid < 128) bcs[tid] = g_bc[n0 + tid];
    int tr = tid >> 4, tc = tid & 15;

    u64 acc[8][4];
    #pragma unroll
    for (int i = 0; i < 8; i++)
        #pragma unroll
        for (int j = 0; j < 4; j++) acc[i][j] = 0ull;

    for (int kt = 0; kt < 2; kt++) {
        #pragma unroll
        for (int r = 0; r < 5; r++) {
            int idx = tid + r * 256;
            int row = idx / 10;
            int c4  = idx - row * 10;
            float4 xa = *(const float4*)&x[(size_t)(m0 + row) * DIN + kt * 40 + c4 * 4];
            float4 wb = *(const float4*)&g_Wc[(n0 + row) * DIN + kt * 40 + c4 * 4];
            As[c4 * 4 + 0][row] = xa.x; As[c4 * 4 + 1][row] = xa.y;
            As[c4 * 4 + 2][row] = xa.z; As[c4 * 4 + 3][row] = xa.w;
            Bs[c4 * 4 + 0][row] = wb.x; Bs[c4 * 4 + 1][row] = wb.y;
            Bs[c4 * 4 + 2][row] = wb.z; Bs[c4 * 4 + 3][row] = wb.w;
        }
        __syncthreads();
        #pragma unroll 4
        for (int k = 0; k < 40; k++) {
            float4 a0 = *(const float4*)&As[k][tr * 8];
            float4 a1 = *(const float4*)&As[k][tr * 8 + 4];
            float4 b0 = *(const float4*)&Bs[k][tc * 8];
            float4 b1 = *(const float4*)&Bs[k][tc * 8 + 4];
            u64 ap[8] = {dup2(a0.x), dup2(a0.y), dup2(a0.z), dup2(a0.w),
                         dup2(a1.x), dup2(a1.y), dup2(a1.z), dup2(a1.w)};
            u64 bp[4] = {pack2(b0.x, b0.y), pack2(b0.z, b0.w),
                         pack2(b1.x, b1.y), pack2(b1.z, b1.w)};
            #pragma unroll
            for (int i = 0; i < 8; i++)
                #pragma unroll
                for (int j = 0; j < 4; j++)
                    fma2(acc[i][j], ap[i], bp[j]);
        }
        __syncthreads();
    }

    float bc0 = bcs[tc * 8 + 0], bc1 = bcs[tc * 8 + 1], bc2 = bcs[tc * 8 + 2], bc3 = bcs[tc * 8 + 3];
    float bc4 = bcs[tc * 8 + 4], bc5 = bcs[tc * 8 + 5], bc6 = bcs[tc * 8 + 6], bc7 = bcs[tc * 8 + 7];
    #pragma unroll
    for (int i = 0; i < 8; i++) {
        float* orow = g_G + (size_t)(m0 + tr * 8 + i) * GDIM + n0 + tc * 8;
        float2 v0 = unpack2(acc[i][0]), v1 = unpack2(acc[i][1]);
        float2 v2 = unpack2(acc[i][2]), v3 = unpack2(acc[i][3]);
        *(float4*)orow       = make_float4(v0.x + bc0, v0.y + bc1, v1.x + bc2, v1.y + bc3);
        *(float4*)(orow + 4) = make_float4(v2.x + bc4, v2.y + bc5, v3.x + bc6, v3.y + bc7);
    }
}

// ---------------- kernel 2: LSTM recurrence segment ----------------
// 128 blocks x 512 threads (16 warps -> 4 per SMSP for latency hiding).
// Thread tid: gate g = tid&3 of hidden unit u = tid>>2 (column j = g*128+u),
// both batch rows -> 2 f32x2 accumulators. Phase B: the quad's 4 gate values
// are exchanged with shfl_xor(1,2); all quad threads redundantly run the
// activation chain; g==0/1 write h / hout. ONE __syncthreads per step.
// Weights per column: 28 f32x2 pairs in regs, 36 pairs in smem stored by
// owning-thread row with stride-38 float2 (conflict-free LDS.128).
__global__ void __launch_bounds__(512, 1) lstm_kernel(const float* __restrict__ w_time, int t0) {
    extern __shared__ float smem[];
    float* hbuf = smem;                        // [2 parity][2 rows][128]
    float2* Wsp = (float2*)(smem + 512);       // [512 thread-rows][WSTRIDE]

    int tid = threadIdx.x;                     // 0..511
    int g = tid & 3;
    int u = tid >> 2;                          // hidden unit 0..127
    int j = (g << 7) + u;                      // gate column
    int b0 = blockIdx.x * 2;

    // stage smem weights into owner-thread rows (coalesced LDG.64 reads)
    for (int i = tid; i < GDIM * KSP; i += 512) {
        int jj = i / KSP, p = i - jj * KSP;
        int trow = ((jj & 127) << 2) + (jj >> 7);
        Wsp[trow * WSTRIDE + p] = g_WTp[i];
    }
    // register weights: 28 pairs for this thread's column
    u64 wreg[KREGP];
    #pragma unroll
    for (int p = 0; p < KREGP; p++) {
        float2 w = g_WTrp[p * GDIM + j];
        wreg[p] = pack2(w.x, w.y);
    }

    // carried state (redundant per quad; identical values)
    int si0 = b0 * HDIM + u, si1 = si0 + HDIM;
    float cc[2], hsA[2], hsB[2], csA[2], csB[2];
    {
        int par0 = t0 & 1;                     // t0 multiple of 128 -> 0
        if (t0 == 0) {
            cc[0] = cc[1] = 0.f;
            hsA[0] = hsA[1] = hsB[0] = hsB[1] = 0.f;
            csA[0] = csA[1] = csB[0] = csB[1] = 0.f;
            if (g == 0) { hbuf[par0 * 256 + u] = 0.f; hbuf[par0 * 256 + 128 + u] = 0.f; }
        } else {
            cc[0] = g_cst[si0]; cc[1] = g_cst[si1];
            hsA[0] = g_hsA[si0]; hsA[1] = g_hsA[si1];
            hsB[0] = g_hsB[si0]; hsB[1] = g_hsB[si1];
            csA[0] = g_csA[si0]; csA[1] = g_csA[si1];
            csB[0] = g_csB[si0]; csB[1] = g_csB[si1];
            if (g == 0) {
                hbuf[par0 * 256 + u]       = g_hst[si0];
                hbuf[par0 * 256 + 128 + u] = g_hst[si1];
            }
        }
    }
    float wt0 = w_time[0], wt1 = w_time[1], wt2 = w_time[2];
    __syncthreads();

    const float* Gp0 = g_G + (size_t)b0 * SEQ * GDIM + j;
    const float* Gp1 = Gp0 + (size_t)SEQ * GDIM;
    float* ho0 = g_hout + (size_t)b0 * SEQ * HDIM + u;
    float* ho1 = ho0 + (size_t)SEQ * HDIM;

    const ulonglong2* Wr = (const ulonglong2*)(Wsp + tid * WSTRIDE);

    float pre0 = Gp0[(size_t)t0 * GDIM];
    float pre1 = Gp1[(size_t)t0 * GDIM];

    int slot = t0 % 3;
    for (int t = t0; t < t0 + TSEG; t++) {
        u64 acc0 = pack2(pre0, 0.f);
        u64 acc1 = pack2(pre1, 0.f);
        int tn = (t + 1 < SEQ) ? (t + 1) : t;  // prefetch next step's G
        pre0 = Gp0[(size_t)tn * GDIM];
        pre1 = Gp1[(size_t)tn * GDIM];

        const ulonglong2* H0 = (const ulonglong2*)(hbuf + (t & 1) * 256);
        const ulonglong2* H1 = H0 + 32;        // +128 floats
        #pragma unroll
        for (int pp = 0; pp < 32; pp++) {      // 4 k per pp (2 pairs)
            ulonglong2 h0 = H0[pp];
            ulonglong2 h1 = H1[pp];
            u64 wA, wB;
            if (pp < KREGP / 2) {              // pairs 0..27 from registers
                wA = wreg[2 * pp]; wB = wreg[2 * pp + 1];
            } else {                           // smem: 2 pairs per LDS.128
                ulonglong2 wp = Wr[pp - KREGP / 2];
                wA = wp.x; wB = wp.y;
            }
            fma2(acc0, wA, h0.x);
            fma2(acc1, wA, h1.x);
            fma2(acc0, wB, h0.y);
            fma2(acc1, wB, h1.y);
        }

        // own gate value per row
        float2 s0 = unpack2(acc0), s1 = unpack2(acc1);
        float va0 = s0.x + s0.y, va1 = s1.x + s1.y;
        // quad exchange: after this, value of gate x (row r) = pick(x^g)
        float bb0 = __shfl_xor_sync(0xffffffffu, va0, 1);
        float bb1 = __shfl_xor_sync(0xffffffffu, va1, 1);
        float cx0 = __shfl_xor_sync(0xffffffffu, va0, 2);
        float cx1 = __shfl_xor_sync(0xffffffffu, va1, 2);
        float dd0 = __shfl_xor_sync(0xffffffffu, bb0, 2);
        float dd1 = __shfl_xor_sync(0xffffffffu, bb1, 2);

        float hoA[2];
        float* hw = hbuf + ((t + 1) & 1) * 256;
        #pragma unroll
        for (int r = 0; r < 2; r++) {
            float va = r ? va1 : va0, vb = r ? bb1 : bb0;
            float vc = r ? cx1 : cx0, vd = r ? dd1 : dd0;
            // gate x value = [va,vb,vc,vd][x^g]
            int i0 = 0 ^ g, i1 = 1 ^ g, i2 = 2 ^ g, i3 = 3 ^ g;
            float ig = (i0 == 0) ? va : (i0 == 1) ? vb : (i0 == 2) ? vc : vd;
            float fg = (i1 == 0) ? va : (i1 == 1) ? vb : (i1 == 2) ? vc : vd;
            float gg = (i2 == 0) ? va : (i2 == 1) ? vb : (i2 == 2) ? vc : vd;
            float og = (i3 == 0) ? va : (i3 == 1) ? vb : (i3 == 2) ? vc : vd;

            float cn = fmaf(sig_p(fg), cc[r], sig_p(ig) * tanh_p(gg));
            float hn = sig_p(og) * tanh_p(C2LOG2E * cn);
            float ho_, co_;
            if (slot == 0)      { hsA[r] = hn; csA[r] = cn; ho_ = hn; co_ = cn; }
            else if (slot == 1) { hsB[r] = hn; csB[r] = cn; ho_ = hn; co_ = cn; }
            else {
                ho_ = wt0 * hsA[r] + wt1 * hsB[r] + wt2 * hn;
                co_ = wt0 * csA[r] + wt1 * csB[r] + wt2 * cn;
            }
            cc[r] = co_;
            hoA[r] = ho_;
        }
        if (g == 0) { hw[u]       = hoA[0]; ho0[(size_t)t * HDIM] = hoA[0]; }
        if (g == 1) { hw[128 + u] = hoA[1]; ho1[(size_t)t * HDIM] = hoA[1]; }

        slot = (slot == 2) ? 0 : slot + 1;
        __syncthreads();                       // the ONLY barrier per step
    }

    // store carried state
    if (g == 0) {
        int parE = (t0 + TSEG) & 1;
        g_hst[si0] = hbuf[parE * 256 + u];
        g_hst[si1] = hbuf[parE * 256 + 128 + u];
        g_cst[si0] = cc[0]; g_cst[si1] = cc[1];
        g_hsA[si0] = hsA[0]; g_hsA[si1] = hsA[1];
        g_hsB[si0] = hsB[0]; g_hsB[si1] = hsB[1];
        g_csA[si0] = csA[0]; g_csA[si1] = csA[1];
        g_csB[si0] = csB[0]; g_csB[si1] = csB[1];
    }
}

// ---------------- kernel 3: logits = hout @ W_br^T + b_br, then log_softmax ----------------
__global__ void __launch_bounds__(256) logits_kernel(const float* __restrict__ W_br,
                                                     const float* __restrict__ b_br,
                                                     float* __restrict__ out) {
    __shared__ float wbr[4 * HDIM];
    __shared__ float bb[4];
    int tid = threadIdx.x;
    for (int i = tid; i < 4 * HDIM; i += 256) wbr[i] = W_br[i];
    if (tid < 4) bb[tid] = b_br[tid];
    __syncthreads();

    int warp = tid >> 5, lane = tid & 31;
    size_t row = (size_t)blockIdx.x * 8 + warp;
    float4 hv = *(const float4*)(g_hout + row * HDIM + lane * 4);

    float p[4];
    #pragma unroll
    for (int o = 0; o < 4; o++) {
        float4 w = *(const float4*)&wbr[o * HDIM + lane * 4];
        p[o] = fmaf(hv.x, w.x, fmaf(hv.y, w.y, fmaf(hv.z, w.z, hv.w * w.w)));
    }
    #pragma unroll
    for (int off = 16; off; off >>= 1) {
        #pragma unroll
        for (int o = 0; o < 4; o++) p[o] += __shfl_xor_sync(0xffffffffu, p[o], off);
    }
    if (lane == 0) {
        float x0 = p[0] + bb[0], x1 = p[1] + bb[1], x2 = p[2] + bb[2], x3 = p[3] + bb[3];
        float m = fmaxf(fmaxf(x0, x1), fmaxf(x2, x3));
        float s = __expf(x0 - m) + __expf(x1 - m) + __expf(x2 - m) + __expf(x3 - m);
        float l = __logf(s);
        *(float4*)(out + row * 4) = make_float4(x0 - m - l, x1 - m - l, x2 - m - l, x3 - m - l);
    }
}

// ---------------- launch ----------------
extern "C" void kernel_launch(void* const* d_in, const int* in_sizes, int n_in,
                              void* d_out, int out_size) {
    const float* x      = (const float*)d_in[0];
    const float* W_in   = (const float*)d_in[1];
    const float* b_in   = (const float*)d_in[2];
    const float* W_ih   = (const float*)d_in[3];
    const float* b_ih   = (const float*)d_in[4];
    const float* W_hh   = (const float*)d_in[5];
    const float* b_hh   = (const float*)d_in[6];
    const float* w_time = (const float*)d_in[7];
    const float* W_br   = (const float*)d_in[8];
    const float* b_br   = (const float*)d_in[9];
    float* out = (float*)d_out;

    combine_kernel<<<GDIM, 128>>>(W_in, b_in, W_ih, b_ih, W_hh, b_hh);
    gemm_kernel<<<dim3(4, 1024), 256>>>(x);

    // hbuf(512 floats) + Wsp(512 * WSTRIDE float2) = 2048 + 155648 = 157696 B
    size_t shmem = 512 * sizeof(float) + (size_t)GDIM * WSTRIDE * sizeof(float2);
    cudaFuncSetAttribute(lstm_kernel, cudaFuncAttributeMaxDynamicSharedMemorySize, (int)shmem);
    for (int s = 0; s < NSEG; s++)
        lstm_kernel<<<BATCH / 2, 512, shmem>>>(w_time, s * TSEG);

    logits_kernel<<<(BATCH * SEQ) / 8, 256>>>(W_br, b_br, out);
}

// round 10
// speedup vs baseline: 1.0695x; 1.0695x over previous
#include <cuda_runtime.h>
#include <cstdint>
#include <cstddef>

#define HDIM   128
#define GDIM   512      // 4*H
#define BATCH  256
#define SEQ    512
#define DIN    80
#define EMB    256
#define KREGP2 8        // weight k-pairs per column in REGISTERS (per k-half)
#define KSPH   24       // weight k-pairs per column in SMEM (per k-half)
#define WROW   98       // float2 stride of one weight smem row (96 used + 2 pad; 784B % 128 = 16 -> conflict-free LDS.128)
#define NSEG   4
#define TSEG   128      // steps per lstm segment launch
#define LOG2E  1.4426950408889634f
#define C2LOG2E 2.8853900817779268f

typedef unsigned long long u64;

// ---------------- device scratch (no allocations allowed) ----------------
__device__ float g_G[(size_t)BATCH * SEQ * GDIM];    // gate pre-activations (input part, prescaled)
__device__ float g_hout[(size_t)BATCH * SEQ * HDIM]; // per-step h_out
__device__ float g_Wc[GDIM * DIN];                   // fused + prescaled  W_ih @ W_in
__device__ float g_bc[GDIM];                         // fused + prescaled  bias
__device__ float2 g_WTrp[2 * KREGP2 * GDIM];         // reg-weight pairs: [kh][p][j] (prescaled)
__device__ float2 g_WTp[256 * 96];                   // smem-weight pairs: [(kh,cg)][m][p'] (prescaled)
// LSTM state carried between segment launches
__device__ float g_hst[BATCH * HDIM];
__device__ float g_cst[BATCH * HDIM];
__device__ float g_hsA[BATCH * HDIM];
__device__ float g_hsB[BATCH * HDIM];
__device__ float g_csA[BATCH * HDIM];
__device__ float g_csB[BATCH * HDIM];

// ---------------- f32x2 helpers ----------------
__device__ __forceinline__ void fma2(u64& d, u64 a, u64 b) {
    asm("fma.rn.f32x2 %0, %1, %2, %0;" : "+l"(d) : "l"(a), "l"(b));
}
__device__ __forceinline__ u64 pack2(float lo, float hi) {
    u64 r; asm("mov.b64 %0, {%1, %2};" : "=l"(r) : "f"(lo), "f"(hi)); return r;
}
__device__ __forceinline__ u64 dup2(float x) {
    u64 r; asm("mov.b64 %0, {%1, %1};" : "=l"(r) : "f"(x)); return r;
}
__device__ __forceinline__ float2 unpack2(u64 v) {
    float2 r; asm("mov.b64 {%0, %1}, %2;" : "=f"(r.x), "=f"(r.y) : "l"(v)); return r;
}

// ---------------- fast activation primitives (inputs prescaled by log2e) ----------------
__device__ __forceinline__ float ex2f(float x) {
    float r; asm("ex2.approx.f32 %0, %1;" : "=f"(r) : "f"(x)); return r;
}
__device__ __forceinline__ float rcpf(float x) {
    float r; asm("rcp.approx.f32 %0, %1;" : "=f"(r) : "f"(x)); return r;
}
__device__ __forceinline__ float sig_p(float g)  { return rcpf(1.0f + ex2f(-g)); }
__device__ __forceinline__ float tanh_p(float g) { return fmaf(-2.0f, rcpf(ex2f(g) + 1.0f), 1.0f); }

// ---------------- kernel 0: fold W_in into W_ih, prescale, pack W_hh^T ----------------
__global__ void combine_kernel(const float* __restrict__ W_in, const float* __restrict__ b_in,
                               const float* __restrict__ W_ih, const float* __restrict__ b_ih,
                               const float* __restrict__ W_hh, const float* __restrict__ b_hh) {
    __shared__ float wih[EMB];
    int j = blockIdx.x;           // 0..511 (gate column)
    int tid = threadIdx.x;        // 128 threads (= k index)
    float s = ((j >> 7) == 2) ? C2LOG2E : LOG2E;   // g-gate rows get 2*log2e
    for (int e = tid; e < EMB; e += 128) wih[e] = W_ih[j * EMB + e];
    if (!(tid & 1)) {
        float2 wp = make_float2(s * W_hh[j * HDIM + tid], s * W_hh[j * HDIM + tid + 1]);
        int kh = tid >> 6;               // k-half
        int p  = (tid & 63) >> 1;        // pair index within half: 0..31
        int cg = j & 127, m = j >> 7;
        if (p < KREGP2) g_WTrp[(kh * KREGP2 + p) * GDIM + j] = wp;
        else            g_WTp[(kh * 128 + cg) * 96 + m * KSPH + (p - KREGP2)] = wp;
    }
    __syncthreads();
    if (tid < DIN) {
        float acc = 0.f;
        #pragma unroll 8
        for (int e = 0; e < EMB; e++) acc = fmaf(wih[e], W_in[e * DIN + tid], acc);
        g_Wc[j * DIN + tid] = s * acc;
    }
    if (tid == 96) {
        float acc = b_ih[j] + b_hh[j];
        #pragma unroll 8
        for (int e = 0; e < EMB; e++) acc = fmaf(wih[e], b_in[e], acc);
        g_bc[j] = s * acc;
    }
}

// ---------------- kernel 1: G[m][j] = x[m][:] . Wc[j][:] + bc[j] ----------------
__global__ void __launch_bounds__(256, 2) gemm_kernel(const float* __restrict__ x) {
    __shared__ float As[40][132];
    __shared__ float Bs[40][132];
    __shared__ float bcs[128];

    int tid = threadIdx.x;
    int n0 = blockIdx.x * 128;
    int m0 = blockIdx.y * 128;
    if (tid < 128) bcs[tid] = g_bc[n0 + tid];
    int tr = tid >> 4, tc = tid & 15;

    u64 acc[8][4];
    #pragma unroll
    for (int i = 0; i < 8; i++)
        #pragma unroll
        for (int j = 0; j < 4; j++) acc[i][j] = 0ull;

    for (int kt = 0; kt < 2; kt++) {
        #pragma unroll
        for (int r = 0; r < 5; r++) {
            int idx = tid + r * 256;
            int row = idx / 10;
            int c4  = idx - row * 10;
            float4 xa = *(const float4*)&x[(size_t)(m0 + row) * DIN + kt * 40 + c4 * 4];
            float4 wb = *(const float4*)&g_Wc[(n0 + row) * DIN + kt * 40 + c4 * 4];
            As[c4 * 4 + 0][row] = xa.x; As[c4 * 4 + 1][row] = xa.y;
            As[c4 * 4 + 2][row] = xa.z; As[c4 * 4 + 3][row] = xa.w;
            Bs[c4 * 4 + 0][row] = wb.x; Bs[c4 * 4 + 1][row] = wb.y;
            Bs[c4 * 4 + 2][row] = wb.z; Bs[c4 * 4 + 3][row] = wb.w;
        }
        __syncthreads();
        #pragma unroll 4
        for (int k = 0; k < 40; k++) {
            float4 a0 = *(const float4*)&As[k][tr * 8];
            float4 a1 = *(const float4*)&As[k][tr * 8 + 4];
            float4 b0 = *(const float4*)&Bs[k][tc * 8];
            float4 b1 = *(const float4*)&Bs[k][tc * 8 + 4];
            u64 ap[8] = {dup2(a0.x), dup2(a0.y), dup2(a0.z), dup2(a0.w),
                         dup2(a1.x), dup2(a1.y), dup2(a1.z), dup2(a1.w)};
            u64 bp[4] = {pack2(b0.x, b0.y), pack2(b0.z, b0.w),
                         pack2(b1.x, b1.y), pack2(b1.z, b1.w)};
            #pragma unroll
            for (int i = 0; i < 8; i++)
                #pragma unroll
                for (int j = 0; j < 4; j++)
                    fma2(acc[i][j], ap[i], bp[j]);
        }
        __syncthreads();
    }

    float bc0 = bcs[tc * 8 + 0], bc1 = bcs[tc * 8 + 1], bc2 = bcs[tc * 8 + 2], bc3 = bcs[tc * 8 + 3];
    float bc4 = bcs[tc * 8 + 4], bc5 = bcs[tc * 8 + 5], bc6 = bcs[tc * 8 + 6], bc7 = bcs[tc * 8 + 7];
    #pragma unroll
    for (int i = 0; i < 8; i++) {
        float* orow = g_G + (size_t)(m0 + tr * 8 + i) * GDIM + n0 + tc * 8;
        float2 v0 = unpack2(acc[i][0]), v1 = unpack2(acc[i][1]);
        float2 v2 = unpack2(acc[i][2]), v3 = unpack2(acc[i][3]);
        *(float4*)orow       = make_float4(v0.x + bc0, v0.y + bc1, v1.x + bc2, v1.y + bc3);
        *(float4*)(orow + 4) = make_float4(v2.x + bc4, v2.y + bc5, v3.x + bc6, v3.y + bc7);
    }
}

// ---------------- kernel 2: LSTM recurrence segment ----------------
// 128 blocks x 512 threads (16 warps -> 4 per SMSP), ZERO redundant work.
// Thread (r, kh, u) [tid = r*256 + kh*128 + u] computes the k in
// [64kh, 64kh+64) partial of all 4 gate columns {u + 128m} for batch row r.
// Per thread: 4 f32x2 accs, 128 fma2, 16 h-LDS.128 (own row+half), 48 w-LDS.128.
// kh=1 threads publish their partial as one float4 to smem; the matching
// (r, kh=0, u) thread adds it -- its 4 m-values ARE gates i,f,g,o of hidden
// unit u, so it runs the single activation chain (no shuffles, no redundancy)
// and writes h. Two __syncthreads per step.
__global__ void __launch_bounds__(512, 1) lstm_kernel(const float* __restrict__ w_time, int t0) {
    extern __shared__ float smem[];
    float* hbuf  = smem;                        // [2 parity][2 rows][128]
    float4* part = (float4*)(smem + 512);       // [2 rows][128]
    float2* Wsp  = (float2*)(smem + 1536);      // [256 rows][WROW]

    int tid = threadIdx.x;                      // 0..511
    int u  = tid & 127;                         // hidden unit / col-group
    int kh = (tid >> 7) & 1;                    // k-half
    int r  = tid >> 8;                          // batch row within block
    int b0 = blockIdx.x * 2;

    // stage smem weights (coalesced; layout matches on-chip layout minus pad)
    for (int i = tid; i < 256 * 96; i += 512) {
        int row = i / 96, q = i - row * 96;
        Wsp[row * WROW + q] = g_WTp[i];
    }
    // register weights: 8 pairs x 4 columns for this (kh, u)
    u64 wreg[4][KREGP2];
    #pragma unroll
    for (int p = 0; p < KREGP2; p++)
        #pragma unroll
        for (int m = 0; m < 4; m++) {
            float2 w = g_WTrp[(kh * KREGP2 + p) * GDIM + m * 128 + u];
            wreg[m][p] = pack2(w.x, w.y);
        }

    const bool act = (kh == 0);
    int si = (b0 + r) * HDIM + u;
    float cc = 0.f, hsA = 0.f, hsB = 0.f, csA = 0.f, csB = 0.f;
    if (act) {
        if (t0 == 0) {
            hbuf[r * 128 + u] = 0.f;            // parity 0
        } else {
            hbuf[r * 128 + u] = g_hst[si];
            cc = g_cst[si];
            hsA = g_hsA[si]; hsB = g_hsB[si];
            csA = g_csA[si]; csB = g_csB[si];
        }
    }
    float wt0 = w_time[0], wt1 = w_time[1], wt2 = w_time[2];
    __syncthreads();

    const float* Gbase = g_G + (size_t)(b0 + r) * SEQ * GDIM + u;
    float* hob = g_hout + (size_t)(b0 + r) * SEQ * HDIM + u;
    const ulonglong2* Wr = (const ulonglong2*)(Wsp + (kh * 128 + u) * WROW);

    float pre[4];
    if (act) {
        #pragma unroll
        for (int m = 0; m < 4; m++)
            pre[m] = Gbase[(size_t)t0 * GDIM + m * 128];
    }

    int slot = t0 % 3;
    for (int t = t0; t < t0 + TSEG; t++) {
        u64 acc[4];
        #pragma unroll
        for (int m = 0; m < 4; m++)
            acc[m] = act ? pack2(pre[m], 0.f) : 0ull;
        if (act) {
            int tn = (t + 1 < SEQ) ? (t + 1) : t;   // prefetch next step's G
            #pragma unroll
            for (int m = 0; m < 4; m++)
                pre[m] = Gbase[(size_t)tn * GDIM + m * 128];
        }

        // k-loop over OWN half: 16 x (1 h-LDS.128 + up-to-4 w-LDS.128 + 8 fma2)
        const ulonglong2* H = (const ulonglong2*)(hbuf + (t & 1) * 256 + r * 128 + kh * 64);
        #pragma unroll
        for (int pp = 0; pp < 16; pp++) {
            ulonglong2 h2 = H[pp];
            #pragma unroll
            for (int m = 0; m < 4; m++) {
                u64 wA, wB;
                if (pp < KREGP2 / 2) {              // pairs 0..7 from registers
                    wA = wreg[m][2 * pp]; wB = wreg[m][2 * pp + 1];
                } else {                            // smem: 2 pairs per LDS.128
                    ulonglong2 wp = Wr[m * (KSPH / 2) + (pp - KREGP2 / 2)];
                    wA = wp.x; wB = wp.y;
                }
                fma2(acc[m], wA, h2.x);
                fma2(acc[m], wB, h2.y);
            }
        }

        float g4[4];
        #pragma unroll
        for (int m = 0; m < 4; m++) { float2 v = unpack2(acc[m]); g4[m] = v.x + v.y; }
        if (!act) part[r * 128 + u] = make_float4(g4[0], g4[1], g4[2], g4[3]);
        __syncthreads();                            // barrier 1: partials ready

        if (act) {
            float4 po = part[r * 128 + u];
            float ig = g4[0] + po.x;
            float fg = g4[1] + po.y;
            float gg = g4[2] + po.z;
            float og = g4[3] + po.w;
            float cn = fmaf(sig_p(fg), cc, sig_p(ig) * tanh_p(gg));
            float hn = sig_p(og) * tanh_p(C2LOG2E * cn);
            float ho_, co_;
            if (slot == 0)      { hsA = hn; csA = cn; ho_ = hn; co_ = cn; }
            else if (slot == 1) { hsB = hn; csB = cn; ho_ = hn; co_ = cn; }
            else {
                ho_ = wt0 * hsA + wt1 * hsB + wt2 * hn;
                co_ = wt0 * csA + wt1 * csB + wt2 * cn;
            }
            cc = co_;
            hbuf[((t + 1) & 1) * 256 + r * 128 + u] = ho_;
            hob[(size_t)t * HDIM] = ho_;
        }
        slot = (slot == 2) ? 0 : slot + 1;
        __syncthreads();                            // barrier 2: new h published
    }

    // store carried state
    if (act) {
        g_hst[si] = hbuf[((t0 + TSEG) & 1) * 256 + r * 128 + u];
        g_cst[si] = cc;
        g_hsA[si] = hsA; g_hsB[si] = hsB;
        g_csA[si] = csA; g_csB[si] = csB;
    }
}

// ---------------- kernel 3: logits = hout @ W_br^T + b_br, then log_softmax ----------------
__global__ void __launch_bounds__(256) logits_kernel(const float* __restrict__ W_br,
                                                     const float* __restrict__ b_br,
                                                     float* __restrict__ out) {
    __shared__ float wbr[4 * HDIM];
    __shared__ float bb[4];
    int tid = threadIdx.x;
    for (int i = tid; i < 4 * HDIM; i += 256) wbr[i] = W_br[i];
    if (tid < 4) bb[tid] = b_br[tid];
    __syncthreads();

    int warp = tid >> 5, lane = tid & 31;
    size_t row = (size_t)blockIdx.x * 8 + warp;
    float4 hv = *(const float4*)(g_hout + row * HDIM + lane * 4);

    float p[4];
    #pragma unroll
    for (int o = 0; o < 4; o++) {
        float4 w = *(const float4*)&wbr[o * HDIM + lane * 4];
        p[o] = fmaf(hv.x, w.x, fmaf(hv.y, w.y, fmaf(hv.z, w.z, hv.w * w.w)));
    }
    #pragma unroll
    for (int off = 16; off; off >>= 1) {
        #pragma unroll
        for (int o = 0; o < 4; o++) p[o] += __shfl_xor_sync(0xffffffffu, p[o], off);
    }
    if (lane == 0) {
        float x0 = p[0] + bb[0], x1 = p[1] + bb[1], x2 = p[2] + bb[2], x3 = p[3] + bb[3];
        float m = fmaxf(fmaxf(x0, x1), fmaxf(x2, x3));
        float s = __expf(x0 - m) + __expf(x1 - m) + __expf(x2 - m) + __expf(x3 - m);
        float l = __logf(s);
        *(float4*)(out + row * 4) = make_float4(x0 - m - l, x1 - m - l, x2 - m - l, x3 - m - l);
    }
}

// ---------------- launch ----------------
extern "C" void kernel_launch(void* const* d_in, const int* in_sizes, int n_in,
                              void* d_out, int out_size) {
    const float* x      = (const float*)d_in[0];
    const float* W_in   = (const float*)d_in[1];
    const float* b_in   = (const float*)d_in[2];
    const float* W_ih   = (const float*)d_in[3];
    const float* b_ih   = (const float*)d_in[4];
    const float* W_hh   = (const float*)d_in[5];
    const float* b_hh   = (const float*)d_in[6];
    const float* w_time = (const float*)d_in[7];
    const float* W_br   = (const float*)d_in[8];
    const float* b_br   = (const float*)d_in[9];
    float* out = (float*)d_out;

    combine_kernel<<<GDIM, 128>>>(W_in, b_in, W_ih, b_ih, W_hh, b_hh);
    gemm_kernel<<<dim3(4, 1024), 256>>>(x);

    // hbuf(512f) + part(256 float4 = 1024f) + Wsp(256 * WROW float2)
    size_t shmem = 1536 * sizeof(float) + (size_t)256 * WROW * sizeof(float2);  // 206848 B
    cudaFuncSetAttribute(lstm_kernel, cudaFuncAttributeMaxDynamicSharedMemorySize, (int)shmem);
    for (int s = 0; s < NSEG; s++)
        lstm_kernel<<<BATCH / 2, 512, shmem>>>(w_time, s * TSEG);

    logits_kernel<<<(BATCH * SEQ) / 8, 256>>>(W_br, b_br, out);
}

// round 11
// speedup vs baseline: 1.3164x; 1.2308x over previous
#include <cuda_runtime.h>
#include <cstdint>
#include <cstddef>

#define HDIM   128
#define GDIM   512      // 4*H
#define BATCH  256
#define SEQ    512
#define DIN    80
#define EMB    256
#define KRP    44       // weight k-pairs per column in REGISTERS (k in [0,88))
#define KSPP   20       // weight k-pairs per column in SMEM (k in [88,128))
#define WROW   42       // float2 stride per thread smem-weight row (40 used + 2 pad; 336B -> 21 16B-chunks, odd -> conflict-free)
#define NSEG   4
#define TSEG   128      // steps per lstm segment launch
#define LOG2E  1.4426950408889634f
#define C2LOG2E 2.8853900817779268f

typedef unsigned long long u64;

// ---------------- device scratch (no allocations allowed) ----------------
__device__ float g_G[(size_t)BATCH * SEQ * GDIM];    // gate pre-activations (input part, prescaled)
__device__ float g_hout[(size_t)BATCH * SEQ * HDIM]; // per-step h_out
__device__ float g_Wc[GDIM * DIN];                   // fused + prescaled  W_ih @ W_in
__device__ float g_bc[GDIM];                         // fused + prescaled  bias
__device__ float2 g_WTrp[KRP * GDIM];                // reg-weight pairs: [p][j] (prescaled)
__device__ float2 g_WTp[GDIM * KSPP];                // smem-weight pairs: [j][p-KRP] (prescaled)
// LSTM state carried between segment launches
__device__ float g_hst[BATCH * HDIM];
__device__ float g_cst[BATCH * HDIM];
__device__ float g_hsA[BATCH * HDIM];
__device__ float g_hsB[BATCH * HDIM];
__device__ float g_csA[BATCH * HDIM];
__device__ float g_csB[BATCH * HDIM];

// ---------------- f32x2 helpers ----------------
__device__ __forceinline__ void fma2(u64& d, u64 a, u64 b) {
    asm("fma.rn.f32x2 %0, %1, %2, %0;" : "+l"(d) : "l"(a), "l"(b));
}
__device__ __forceinline__ u64 pack2(float lo, float hi) {
    u64 r; asm("mov.b64 %0, {%1, %2};" : "=l"(r) : "f"(lo), "f"(hi)); return r;
}
__device__ __forceinline__ u64 dup2(float x) {
    u64 r; asm("mov.b64 %0, {%1, %1};" : "=l"(r) : "f"(x)); return r;
}
__device__ __forceinline__ float2 unpack2(u64 v) {
    float2 r; asm("mov.b64 {%0, %1}, %2;" : "=f"(r.x), "=f"(r.y) : "l"(v)); return r;
}

// ---------------- fast activation primitives (inputs prescaled by log2e) ----------------
__device__ __forceinline__ float ex2f(float x) {
    float r; asm("ex2.approx.f32 %0, %1;" : "=f"(r) : "f"(x)); return r;
}
__device__ __forceinline__ float rcpf(float x) {
    float r; asm("rcp.approx.f32 %0, %1;" : "=f"(r) : "f"(x)); return r;
}
__device__ __forceinline__ float sig_p(float g)  { return rcpf(1.0f + ex2f(-g)); }
__device__ __forceinline__ float tanh_p(float g) { return fmaf(-2.0f, rcpf(ex2f(g) + 1.0f), 1.0f); }

// ---------------- kernel 0: fold W_in into W_ih, prescale, pack W_hh^T ----------------
__global__ void combine_kernel(const float* __restrict__ W_in, const float* __restrict__ b_in,
                               const float* __restrict__ W_ih, const float* __restrict__ b_ih,
                               const float* __restrict__ W_hh, const float* __restrict__ b_hh) {
    __shared__ float wih[EMB];
    int j = blockIdx.x;           // 0..511 (gate column)
    int tid = threadIdx.x;        // 128 threads (= k index)
    float s = ((j >> 7) == 2) ? C2LOG2E : LOG2E;   // g-gate rows get 2*log2e
    for (int e = tid; e < EMB; e += 128) wih[e] = W_ih[j * EMB + e];
    if (!(tid & 1)) {
        float2 wp = make_float2(s * W_hh[j * HDIM + tid], s * W_hh[j * HDIM + tid + 1]);
        int p = tid >> 1;                // pair index 0..63
        if (p < KRP) g_WTrp[p * GDIM + j] = wp;
        else         g_WTp[j * KSPP + (p - KRP)] = wp;
    }
    __syncthreads();
    if (tid < DIN) {
        float acc = 0.f;
        #pragma unroll 8
        for (int e = 0; e < EMB; e++) acc = fmaf(wih[e], W_in[e * DIN + tid], acc);
        g_Wc[j * DIN + tid] = s * acc;
    }
    if (tid == 96) {
        float acc = b_ih[j] + b_hh[j];
        #pragma unroll 8
        for (int e = 0; e < EMB; e++) acc = fmaf(wih[e], b_in[e], acc);
        g_bc[j] = s * acc;
    }
}

// ---------------- kernel 1: G[m][j] = x[m][:] . Wc[j][:] + bc[j] ----------------
__global__ void __launch_bounds__(256, 2) gemm_kernel(const float* __restrict__ x) {
    __shared__ float As[40][132];
    __shared__ float Bs[40][132];
    __shared__ float bcs[128];

    int tid = threadIdx.x;
    int n0 = blockIdx.x * 128;
    int m0 = blockIdx.y * 128;
    if (tid < 128) bcs[tid] = g_bc[n0 + tid];
    int tr = tid >> 4, tc = tid & 15;

    u64 acc[8][4];
    #pragma unroll
    for (int i = 0; i < 8; i++)
        #pragma unroll
        for (int j = 0; j < 4; j++) acc[i][j] = 0ull;

    for (int kt = 0; kt < 2; kt++) {
        #pragma unroll
        for (int r = 0; r < 5; r++) {
            int idx = tid + r * 256;
            int row = idx / 10;
            int c4  = idx - row * 10;
            float4 xa = *(const float4*)&x[(size_t)(m0 + row) * DIN + kt * 40 + c4 * 4];
            float4 wb = *(const float4*)&g_Wc[(n0 + row) * DIN + kt * 40 + c4 * 4];
            As[c4 * 4 + 0][row] = xa.x; As[c4 * 4 + 1][row] = xa.y;
            As[c4 * 4 + 2][row] = xa.z; As[c4 * 4 + 3][row] = xa.w;
            Bs[c4 * 4 + 0][row] = wb.x; Bs[c4 * 4 + 1][row] = wb.y;
            Bs[c4 * 4 + 2][row] = wb.z; Bs[c4 * 4 + 3][row] = wb.w;
        }
        __syncthreads();
        #pragma unroll 4
        for (int k = 0; k < 40; k++) {
            float4 a0 = *(const float4*)&As[k][tr * 8];
            float4 a1 = *(const float4*)&As[k][tr * 8 + 4];
            float4 b0 = *(const float4*)&Bs[k][tc * 8];
            float4 b1 = *(const float4*)&Bs[k][tc * 8 + 4];
            u64 ap[8] = {dup2(a0.x), dup2(a0.y), dup2(a0.z), dup2(a0.w),
                         dup2(a1.x), dup2(a1.y), dup2(a1.z), dup2(a1.w)};
            u64 bp[4] = {pack2(b0.x, b0.y), pack2(b0.z, b0.w),
                         pack2(b1.x, b1.y), pack2(b1.z, b1.w)};
            #pragma unroll
            for (int i = 0; i < 8; i++)
                #pragma unroll
                for (int j = 0; j < 4; j++)
                    fma2(acc[i][j], ap[i], bp[j]);
        }
        __syncthreads();
    }

    float bc0 = bcs[tc * 8 + 0], bc1 = bcs[tc * 8 + 1], bc2 = bcs[tc * 8 + 2], bc3 = bcs[tc * 8 + 3];
    float bc4 = bcs[tc * 8 + 4], bc5 = bcs[tc * 8 + 5], bc6 = bcs[tc * 8 + 6], bc7 = bcs[tc * 8 + 7];
    #pragma unroll
    for (int i = 0; i < 8; i++) {
        float* orow = g_G + (size_t)(m0 + tr * 8 + i) * GDIM + n0 + tc * 8;
        float2 v0 = unpack2(acc[i][0]), v1 = unpack2(acc[i][1]);
        float2 v2 = unpack2(acc[i][2]), v3 = unpack2(acc[i][3]);
        *(float4*)orow       = make_float4(v0.x + bc0, v0.y + bc1, v1.x + bc2, v1.y + bc3);
        *(float4*)(orow + 4) = make_float4(v2.x + bc4, v2.y + bc5, v3.x + bc6, v3.y + bc7);
    }
}

// ---------------- kernel 2: LSTM recurrence segment ----------------
// 128 blocks x 256 threads (8 warps -> 2 per SMSP). Weights read ONCE.
// Thread (half = tid>>7, u = tid&127) owns columns cA = half*128+u and
// cB = cA+256 for BOTH batch rows (4 f32x2 accumulators, 256 fma2/step).
// half=0 thus owns gates (i,g) of hidden unit u; half=1 owns (f,o) of the
// SAME unit -> phase B needs only one float4 smem exchange, then the half=0
// thread runs both rows' activation chains. Weights: 44 pairs/col in regs
// (176 regs), 20 pairs/col in smem (82KB -> 640 crossbar cyc/step).
__global__ void __launch_bounds__(256, 1) lstm_kernel(const float* __restrict__ w_time, int t0) {
    extern __shared__ float smem[];
    float*  hbuf = smem;                       // [2 parity][2 rows][128]
    float4* fx   = (float4*)(smem + 512);      // [128]: (f_r0, f_r1, o_r0, o_r1)
    float2* Wsp  = (float2*)(smem + 1024);     // [256 thread rows][WROW]

    int tid  = threadIdx.x;                    // 0..255
    int half = tid >> 7;                       // 0: (i,g) owner; 1: (f,o) owner
    int u    = tid & 127;                      // hidden unit
    int cA   = (half << 7) + u;                // m = half
    int cB   = cA + 256;                       // m = half + 2
    int b0   = blockIdx.x * 2;

    // stage this thread's smem weight row: [cA pairs 44..63][cB pairs 44..63]
    {
        const float4* srcA = (const float4*)(g_WTp + cA * KSPP);
        const float4* srcB = (const float4*)(g_WTp + cB * KSPP);
        float4* dst = (float4*)(Wsp + tid * WROW);
        #pragma unroll
        for (int i = 0; i < KSPP / 2; i++) dst[i] = srcA[i];
        #pragma unroll
        for (int i = 0; i < KSPP / 2; i++) dst[KSPP / 2 + i] = srcB[i];
    }
    // register weights: 44 pairs per column (coalesced float2 over j)
    u64 wrA[KRP], wrB[KRP];
    #pragma unroll
    for (int p = 0; p < KRP; p++) {
        float2 a = g_WTrp[p * GDIM + cA];
        float2 b = g_WTrp[p * GDIM + cB];
        wrA[p] = pack2(a.x, a.y);
        wrB[p] = pack2(b.x, b.y);
    }

    // carried state (half==0 threads only)
    float cc[2], hsA[2], hsB[2], csA[2], csB[2];
    int si0 = b0 * HDIM + u, si1 = si0 + HDIM;
    if (half == 0) {
        int par0 = t0 & 1;
        if (t0 == 0) {
            cc[0] = cc[1] = 0.f;
            hsA[0] = hsA[1] = hsB[0] = hsB[1] = 0.f;
            csA[0] = csA[1] = csB[0] = csB[1] = 0.f;
            hbuf[par0 * 256 + u] = 0.f;
            hbuf[par0 * 256 + 128 + u] = 0.f;
        } else {
            cc[0] = g_cst[si0]; cc[1] = g_cst[si1];
            hsA[0] = g_hsA[si0]; hsA[1] = g_hsA[si1];
            hsB[0] = g_hsB[si0]; hsB[1] = g_hsB[si1];
            csA[0] = g_csA[si0]; csA[1] = g_csA[si1];
            csB[0] = g_csB[si0]; csB[1] = g_csB[si1];
            hbuf[par0 * 256 + u]       = g_hst[si0];
            hbuf[par0 * 256 + 128 + u] = g_hst[si1];
        }
    }
    float wt0 = w_time[0], wt1 = w_time[1], wt2 = w_time[2];
    __syncthreads();

    // G streams: (col, row) x 4
    const float* GA0 = g_G + (size_t)b0 * SEQ * GDIM + cA;
    const float* GB0 = GA0 + 256;
    const float* GA1 = GA0 + (size_t)SEQ * GDIM;
    const float* GB1 = GA1 + 256;
    float* ho0 = g_hout + (size_t)b0 * SEQ * HDIM + u;
    float* ho1 = ho0 + (size_t)SEQ * HDIM;

    const ulonglong2* WrowA = (const ulonglong2*)(Wsp + tid * WROW);          // 10 x 2 pairs
    const ulonglong2* WrowB = (const ulonglong2*)(Wsp + tid * WROW + KSPP);   // 10 x 2 pairs

    float preA0 = GA0[(size_t)t0 * GDIM], preB0 = GB0[(size_t)t0 * GDIM];
    float preA1 = GA1[(size_t)t0 * GDIM], preB1 = GB1[(size_t)t0 * GDIM];

    int slot = t0 % 3;
    for (int t = t0; t < t0 + TSEG; t++) {
        u64 aA0 = pack2(preA0, 0.f), aB0 = pack2(preB0, 0.f);
        u64 aA1 = pack2(preA1, 0.f), aB1 = pack2(preB1, 0.f);
        int tn = (t + 1 < SEQ) ? (t + 1) : t;     // prefetch next step's G
        preA0 = GA0[(size_t)tn * GDIM];
        preB0 = GB0[(size_t)tn * GDIM];
        preA1 = GA1[(size_t)tn * GDIM];
        preB1 = GB1[(size_t)tn * GDIM];

        const ulonglong2* H0 = (const ulonglong2*)(hbuf + (t & 1) * 256);
        const ulonglong2* H1 = H0 + 32;           // +128 floats
        #pragma unroll
        for (int q = 0; q < 32; q++) {            // pairs 2q, 2q+1 (4 k values)
            ulonglong2 h0 = H0[q];
            ulonglong2 h1 = H1[q];
            u64 wAa, wAb, wBa, wBb;
            if (2 * q < KRP) {                    // q < 22: both pairs from regs
                wAa = wrA[2 * q]; wAb = wrA[2 * q + 1];
                wBa = wrB[2 * q]; wBb = wrB[2 * q + 1];
            } else {                              // smem: 2 pairs per LDS.128
                ulonglong2 wA2 = WrowA[q - KRP / 2];
                ulonglong2 wB2 = WrowB[q - KRP / 2];
                wAa = wA2.x; wAb = wA2.y;
                wBa = wB2.x; wBb = wB2.y;
            }
            fma2(aA0, wAa, h0.x);
            fma2(aA1, wAa, h1.x);
            fma2(aB0, wBa, h0.x);
            fma2(aB1, wBa, h1.x);
            fma2(aA0, wAb, h0.y);
            fma2(aA1, wAb, h1.y);
            fma2(aB0, wBb, h0.y);
            fma2(aB1, wBb, h1.y);
        }

        float2 vA0 = unpack2(aA0), vA1 = unpack2(aA1);
        float2 vB0 = unpack2(aB0), vB1 = unpack2(aB1);
        float gA0 = vA0.x + vA0.y, gA1 = vA1.x + vA1.y;   // col cA, rows 0/1
        float gB0 = vB0.x + vB0.y, gB1 = vB1.x + vB1.y;   // col cB, rows 0/1

        if (half == 1)                            // publish (f_r0, f_r1, o_r0, o_r1)
            fx[u] = make_float4(gA0, gA1, gB0, gB1);
        __syncthreads();                          // barrier 1: f,o partials ready

        if (half == 0) {                          // owns i (gA*) and g (gB*)
            float4 fo = fx[u];
            float* hw = hbuf + ((t + 1) & 1) * 256;
            #pragma unroll
            for (int r = 0; r < 2; r++) {
                float ig = r ? gA1 : gA0;
                float gg = r ? gB1 : gB0;
                float fg = r ? fo.y : fo.x;
                float og = r ? fo.w : fo.z;
                float cn = fmaf(sig_p(fg), cc[r], sig_p(ig) * tanh_p(gg));
                float hn = sig_p(og) * tanh_p(C2LOG2E * cn);
                float ho_, co_;
                if (slot == 0)      { hsA[r] = hn; csA[r] = cn; ho_ = hn; co_ = cn; }
                else if (slot == 1) { hsB[r] = hn; csB[r] = cn; ho_ = hn; co_ = cn; }
                else {
                    ho_ = wt0 * hsA[r] + wt1 * hsB[r] + wt2 * hn;
                    co_ = wt0 * csA[r] + wt1 * csB[r] + wt2 * cn;
                }
                cc[r] = co_;
                hw[r * 128 + u] = ho_;
                (r ? ho1 : ho0)[(size_t)t * HDIM] = ho_;
            }
        }
        slot = (slot == 2) ? 0 : slot + 1;
        __syncthreads();                          // barrier 2: new h published
    }

    // store carried state
    if (half == 0) {
        int parE = (t0 + TSEG) & 1;
        g_hst[si0] = hbuf[parE * 256 + u];
        g_hst[si1] = hbuf[parE * 256 + 128 + u];
        g_cst[si0] = cc[0]; g_cst[si1] = cc[1];
        g_hsA[si0] = hsA[0]; g_hsA[si1] = hsA[1];
        g_hsB[si0] = hsB[0]; g_hsB[si1] = hsB[1];
        g_csA[si0] = csA[0]; g_csA[si1] = csA[1];
        g_csB[si0] = csB[0]; g_csB[si1] = csB[1];
    }
}

// ---------------- kernel 3: logits = hout @ W_br^T + b_br, then log_softmax ----------------
__global__ void __launch_bounds__(256) logits_kernel(const float* __restrict__ W_br,
                                                     const float* __restrict__ b_br,
                                                     float* __restrict__ out) {
    __shared__ float wbr[4 * HDIM];
    __shared__ float bb[4];
    int tid = threadIdx.x;
    for (int i = tid; i < 4 * HDIM; i += 256) wbr[i] = W_br[i];
    if (tid < 4) bb[tid] = b_br[tid];
    __syncthreads();

    int warp = tid >> 5, lane = tid & 31;
    size_t row = (size_t)blockIdx.x * 8 + warp;
    float4 hv = *(const float4*)(g_hout + row * HDIM + lane * 4);

    float p[4];
    #pragma unroll
    for (int o = 0; o < 4; o++) {
        float4 w = *(const float4*)&wbr[o * HDIM + lane * 4];
        p[o] = fmaf(hv.x, w.x, fmaf(hv.y, w.y, fmaf(hv.z, w.z, hv.w * w.w)));
    }
    #pragma unroll
    for (int off = 16; off; off >>= 1) {
        #pragma unroll
        for (int o = 0; o < 4; o++) p[o] += __shfl_xor_sync(0xffffffffu, p[o], off);
    }
    if (lane == 0) {
        float x0 = p[0] + bb[0], x1 = p[1] + bb[1], x2 = p[2] + bb[2], x3 = p[3] + bb[3];
        float m = fmaxf(fmaxf(x0, x1), fmaxf(x2, x3));
        float s = __expf(x0 - m) + __expf(x1 - m) + __expf(x2 - m) + __expf(x3 - m);
        float l = __logf(s);
        *(float4*)(out + row * 4) = make_float4(x0 - m - l, x1 - m - l, x2 - m - l, x3 - m - l);
    }
}

// ---------------- launch ----------------
extern "C" void kernel_launch(void* const* d_in, const int* in_sizes, int n_in,
                              void* d_out, int out_size) {
    const float* x      = (const float*)d_in[0];
    const float* W_in   = (const float*)d_in[1];
    const float* b_in   = (const float*)d_in[2];
    const float* W_ih   = (const float*)d_in[3];
    const float* b_ih   = (const float*)d_in[4];
    const float* W_hh   = (const float*)d_in[5];
    const float* b_hh   = (const float*)d_in[6];
    const float* w_time = (const float*)d_in[7];
    const float* W_br   = (const float*)d_in[8];
    const float* b_br   = (const float*)d_in[9];
    float* out = (float*)d_out;

    combine_kernel<<<GDIM, 128>>>(W_in, b_in, W_ih, b_ih, W_hh, b_hh);
    gemm_kernel<<<dim3(4, 1024), 256>>>(x);

    // hbuf(512f) + fx(128 float4 = 512f) + Wsp(256 * WROW float2)
    size_t shmem = 1024 * sizeof(float) + (size_t)256 * WROW * sizeof(float2);  // 90112 B
    cudaFuncSetAttribute(lstm_kernel, cudaFuncAttributeMaxDynamicSharedMemorySize, (int)shmem);
    for (int s = 0; s < NSEG; s++)
        lstm_kernel<<<BATCH / 2, 256, shmem>>>(w_time, s * TSEG);

    logits_kernel<<<(BATCH * SEQ) / 8, 256>>>(W_br, b_br, out);
}

// round 12
// speedup vs baseline: 1.4860x; 1.1289x over previous
#include <cuda_runtime.h>
#include <cstdint>
#include <cstddef>

#define HDIM   128
#define GDIM   512      // 4*H
#define BATCH  256
#define SEQ    512
#define DIN    80
#define EMB    256
#define KRP    32       // weight k-pairs per column in REGISTERS (k in [0,64))
#define KSPP   32       // weight k-pairs per column in SMEM (k in [64,128))
#define WROW   66       // float2 stride per thread smem-weight row (64 used + 2 pad; 528B = 33 16B-chunks, odd -> conflict-free)
#define NSEG   4
#define TSEG   128      // steps per lstm segment launch
#define LOG2E  1.4426950408889634f
#define C2LOG2E 2.8853900817779268f

typedef unsigned long long u64;

// ---------------- device scratch (no allocations allowed) ----------------
__device__ float g_G[(size_t)BATCH * SEQ * GDIM];    // gate pre-activations (input part, prescaled)
__device__ float g_hout[(size_t)BATCH * SEQ * HDIM]; // per-step h_out
__device__ float g_Wc[GDIM * DIN];                   // fused + prescaled  W_ih @ W_in
__device__ float g_bc[GDIM];                         // fused + prescaled  bias
__device__ float2 g_WTrp[KRP * GDIM];                // reg-weight pairs: [p][j] (prescaled)
__device__ float2 g_WTp[GDIM * KSPP];                // smem-weight pairs: [j][p-KRP] (prescaled)
// LSTM state carried between segment launches
__device__ float g_hst[BATCH * HDIM];
__device__ float g_cst[BATCH * HDIM];
__device__ float g_hsA[BATCH * HDIM];
__device__ float g_hsB[BATCH * HDIM];
__device__ float g_csA[BATCH * HDIM];
__device__ float g_csB[BATCH * HDIM];

// ---------------- f32x2 helpers ----------------
__device__ __forceinline__ void fma2(u64& d, u64 a, u64 b) {
    asm("fma.rn.f32x2 %0, %1, %2, %0;" : "+l"(d) : "l"(a), "l"(b));
}
__device__ __forceinline__ u64 pack2(float lo, float hi) {
    u64 r; asm("mov.b64 %0, {%1, %2};" : "=l"(r) : "f"(lo), "f"(hi)); return r;
}
__device__ __forceinline__ u64 dup2(float x) {
    u64 r; asm("mov.b64 %0, {%1, %1};" : "=l"(r) : "f"(x)); return r;
}
__device__ __forceinline__ float2 unpack2(u64 v) {
    float2 r; asm("mov.b64 {%0, %1}, %2;" : "=f"(r.x), "=f"(r.y) : "l"(v)); return r;
}

// ---------------- fast activation primitives (inputs prescaled by log2e) ----------------
__device__ __forceinline__ float ex2f(float x) {
    float r; asm("ex2.approx.f32 %0, %1;" : "=f"(r) : "f"(x)); return r;
}
__device__ __forceinline__ float rcpf(float x) {
    float r; asm("rcp.approx.f32 %0, %1;" : "=f"(r) : "f"(x)); return r;
}
__device__ __forceinline__ float sig_p(float g)  { return rcpf(1.0f + ex2f(-g)); }
__device__ __forceinline__ float tanh_p(float g) { return fmaf(-2.0f, rcpf(ex2f(g) + 1.0f), 1.0f); }

// ---------------- kernel 0: fold W_in into W_ih, prescale, pack W_hh^T ----------------
__global__ void combine_kernel(const float* __restrict__ W_in, const float* __restrict__ b_in,
                               const float* __restrict__ W_ih, const float* __restrict__ b_ih,
                               const float* __restrict__ W_hh, const float* __restrict__ b_hh) {
    __shared__ float wih[EMB];
    int j = blockIdx.x;           // 0..511 (gate column)
    int tid = threadIdx.x;        // 128 threads (= k index)
    float s = ((j >> 7) == 2) ? C2LOG2E : LOG2E;   // g-gate rows get 2*log2e
    for (int e = tid; e < EMB; e += 128) wih[e] = W_ih[j * EMB + e];
    if (!(tid & 1)) {
        float2 wp = make_float2(s * W_hh[j * HDIM + tid], s * W_hh[j * HDIM + tid + 1]);
        int p = tid >> 1;                // pair index 0..63
        if (p < KRP) g_WTrp[p * GDIM + j] = wp;
        else         g_WTp[j * KSPP + (p - KRP)] = wp;
    }
    __syncthreads();
    if (tid < DIN) {
        float acc = 0.f;
        #pragma unroll 8
        for (int e = 0; e < EMB; e++) acc = fmaf(wih[e], W_in[e * DIN + tid], acc);
        g_Wc[j * DIN + tid] = s * acc;
    }
    if (tid == 96) {
        float acc = b_ih[j] + b_hh[j];
        #pragma unroll 8
        for (int e = 0; e < EMB; e++) acc = fmaf(wih[e], b_in[e], acc);
        g_bc[j] = s * acc;
    }
}

// ---------------- kernel 1: G[m][j] = x[m][:] . Wc[j][:] + bc[j] ----------------
__global__ void __launch_bounds__(256, 2) gemm_kernel(const float* __restrict__ x) {
    __shared__ float As[40][132];
    __shared__ float Bs[40][132];
    __shared__ float bcs[128];

    int tid = threadIdx.x;
    int n0 = blockIdx.x * 128;
    int m0 = blockIdx.y * 128;
    if (tid < 128) bcs[tid] = g_bc[n0 + tid];
    int tr = tid >> 4, tc = tid & 15;

    u64 acc[8][4];
    #pragma unroll
    for (int i = 0; i < 8; i++)
        #pragma unroll
        for (int j = 0; j < 4; j++) acc[i][j] = 0ull;

    for (int kt = 0; kt < 2; kt++) {
        #pragma unroll
        for (int r = 0; r < 5; r++) {
            int idx = tid + r * 256;
            int row = idx / 10;
            int c4  = idx - row * 10;
            float4 xa = *(const float4*)&x[(size_t)(m0 + row) * DIN + kt * 40 + c4 * 4];
            float4 wb = *(const float4*)&g_Wc[(n0 + row) * DIN + kt * 40 + c4 * 4];
            As[c4 * 4 + 0][row] = xa.x; As[c4 * 4 + 1][row] = xa.y;
            As[c4 * 4 + 2][row] = xa.z; As[c4 * 4 + 3][row] = xa.w;
            Bs[c4 * 4 + 0][row] = wb.x; Bs[c4 * 4 + 1][row] = wb.y;
            Bs[c4 * 4 + 2][row] = wb.z; Bs[c4 * 4 + 3][row] = wb.w;
        }
        __syncthreads();
        #pragma unroll 4
        for (int k = 0; k < 40; k++) {
            float4 a0 = *(const float4*)&As[k][tr * 8];
            float4 a1 = *(const float4*)&As[k][tr * 8 + 4];
            float4 b0 = *(const float4*)&Bs[k][tc * 8];
            float4 b1 = *(const float4*)&Bs[k][tc * 8 + 4];
            u64 ap[8] = {dup2(a0.x), dup2(a0.y), dup2(a0.z), dup2(a0.w),
                         dup2(a1.x), dup2(a1.y), dup2(a1.z), dup2(a1.w)};
            u64 bp[4] = {pack2(b0.x, b0.y), pack2(b0.z, b0.w),
                         pack2(b1.x, b1.y), pack2(b1.z, b1.w)};
            #pragma unroll
            for (int i = 0; i < 8; i++)
                #pragma unroll
                for (int j = 0; j < 4; j++)
                    fma2(acc[i][j], ap[i], bp[j]);
        }
        __syncthreads();
    }

    float bc0 = bcs[tc * 8 + 0], bc1 = bcs[tc * 8 + 1], bc2 = bcs[tc * 8 + 2], bc3 = bcs[tc * 8 + 3];
    float bc4 = bcs[tc * 8 + 4], bc5 = bcs[tc * 8 + 5], bc6 = bcs[tc * 8 + 6], bc7 = bcs[tc * 8 + 7];
    #pragma unroll
    for (int i = 0; i < 8; i++) {
        float* orow = g_G + (size_t)(m0 + tr * 8 + i) * GDIM + n0 + tc * 8;
        float2 v0 = unpack2(acc[i][0]), v1 = unpack2(acc[i][1]);
        float2 v2 = unpack2(acc[i][2]), v3 = unpack2(acc[i][3]);
        *(float4*)orow       = make_float4(v0.x + bc0, v0.y + bc1, v1.x + bc2, v1.y + bc3);
        *(float4*)(orow + 4) = make_float4(v2.x + bc4, v2.y + bc5, v3.x + bc6, v3.y + bc7);
    }
}

// ---------------- kernel 2: LSTM recurrence segment ----------------
// 128 blocks x 256 threads (8 warps -> 2 per SMSP). Weights read ONCE.
// Thread (half = tid>>7, u = tid&127) owns columns cA = half*128+u and
// cB = cA+256 for BOTH batch rows (4 f32x2 accumulators, 256 fma2/step).
// half=0 owns gates (i,g) of unit u; half=1 owns (f,o) -> phase B is a single
// float4 smem exchange. Weight split 32 reg-pairs + 32 smem-pairs per column:
// ~48 registers freed vs the 44/20 split so ptxas can software-pipeline the
// LDS stream instead of exposing the 29-cyc latency on every load.
__global__ void __launch_bounds__(256, 1) lstm_kernel(const float* __restrict__ w_time, int t0) {
    extern __shared__ float smem[];
    float*  hbuf = smem;                       // [2 parity][2 rows][128]
    float4* fx   = (float4*)(smem + 512);      // [128]: (f_r0, f_r1, o_r0, o_r1)
    float2* Wsp  = (float2*)(smem + 1024);     // [256 thread rows][WROW]

    int tid  = threadIdx.x;                    // 0..255
    int half = tid >> 7;                       // 0: (i,g) owner; 1: (f,o) owner
    int u    = tid & 127;                      // hidden unit
    int cA   = (half << 7) + u;                // m = half
    int cB   = cA + 256;                       // m = half + 2
    int b0   = blockIdx.x * 2;

    // stage this thread's smem weight row: [cA pairs 32..63][cB pairs 32..63]
    {
        const float4* srcA = (const float4*)(g_WTp + cA * KSPP);
        const float4* srcB = (const float4*)(g_WTp + cB * KSPP);
        float4* dst = (float4*)(Wsp + tid * WROW);
        #pragma unroll
        for (int i = 0; i < KSPP / 2; i++) dst[i] = srcA[i];
        #pragma unroll
        for (int i = 0; i < KSPP / 2; i++) dst[KSPP / 2 + i] = srcB[i];
    }
    // register weights: 32 pairs per column (coalesced float2 over j)
    u64 wrA[KRP], wrB[KRP];
    #pragma unroll
    for (int p = 0; p < KRP; p++) {
        float2 a = g_WTrp[p * GDIM + cA];
        float2 b = g_WTrp[p * GDIM + cB];
        wrA[p] = pack2(a.x, a.y);
        wrB[p] = pack2(b.x, b.y);
    }

    // carried state (half==0 threads only)
    float cc[2], hsA[2], hsB[2], csA[2], csB[2];
    int si0 = b0 * HDIM + u, si1 = si0 + HDIM;
    if (half == 0) {
        int par0 = t0 & 1;
        if (t0 == 0) {
            cc[0] = cc[1] = 0.f;
            hsA[0] = hsA[1] = hsB[0] = hsB[1] = 0.f;
            csA[0] = csA[1] = csB[0] = csB[1] = 0.f;
            hbuf[par0 * 256 + u] = 0.f;
            hbuf[par0 * 256 + 128 + u] = 0.f;
        } else {
            cc[0] = g_cst[si0]; cc[1] = g_cst[si1];
            hsA[0] = g_hsA[si0]; hsA[1] = g_hsA[si1];
            hsB[0] = g_hsB[si0]; hsB[1] = g_hsB[si1];
            csA[0] = g_csA[si0]; csA[1] = g_csA[si1];
            csB[0] = g_csB[si0]; csB[1] = g_csB[si1];
            hbuf[par0 * 256 + u]       = g_hst[si0];
            hbuf[par0 * 256 + 128 + u] = g_hst[si1];
        }
    }
    float wt0 = w_time[0], wt1 = w_time[1], wt2 = w_time[2];
    __syncthreads();

    // G streams: (col, row) x 4
    const float* GA0 = g_G + (size_t)b0 * SEQ * GDIM + cA;
    const float* GB0 = GA0 + 256;
    const float* GA1 = GA0 + (size_t)SEQ * GDIM;
    const float* GB1 = GA1 + 256;
    float* ho0 = g_hout + (size_t)b0 * SEQ * HDIM + u;
    float* ho1 = ho0 + (size_t)SEQ * HDIM;

    const ulonglong2* WrowA = (const ulonglong2*)(Wsp + tid * WROW);          // 16 x 2 pairs
    const ulonglong2* WrowB = (const ulonglong2*)(Wsp + tid * WROW + KSPP);   // 16 x 2 pairs

    float preA0 = GA0[(size_t)t0 * GDIM], preB0 = GB0[(size_t)t0 * GDIM];
    float preA1 = GA1[(size_t)t0 * GDIM], preB1 = GB1[(size_t)t0 * GDIM];

    int slot = t0 % 3;
    for (int t = t0; t < t0 + TSEG; t++) {
        u64 aA0 = pack2(preA0, 0.f), aB0 = pack2(preB0, 0.f);
        u64 aA1 = pack2(preA1, 0.f), aB1 = pack2(preB1, 0.f);
        int tn = (t + 1 < SEQ) ? (t + 1) : t;     // prefetch next step's G
        preA0 = GA0[(size_t)tn * GDIM];
        preB0 = GB0[(size_t)tn * GDIM];
        preA1 = GA1[(size_t)tn * GDIM];
        preB1 = GB1[(size_t)tn * GDIM];

        const ulonglong2* H0 = (const ulonglong2*)(hbuf + (t & 1) * 256);
        const ulonglong2* H1 = H0 + 32;           // +128 floats
        #pragma unroll
        for (int q = 0; q < 32; q++) {            // pairs 2q, 2q+1 (4 k values)
            ulonglong2 h0 = H0[q];
            ulonglong2 h1 = H1[q];
            u64 wAa, wAb, wBa, wBb;
            if (2 * q < KRP) {                    // q < 16: both pairs from regs
                wAa = wrA[2 * q]; wAb = wrA[2 * q + 1];
                wBa = wrB[2 * q]; wBb = wrB[2 * q + 1];
            } else {                              // smem: 2 pairs per LDS.128
                ulonglong2 wA2 = WrowA[q - KRP / 2];
                ulonglong2 wB2 = WrowB[q - KRP / 2];
                wAa = wA2.x; wAb = wA2.y;
                wBa = wB2.x; wBb = wB2.y;
            }
            fma2(aA0, wAa, h0.x);
            fma2(aA1, wAa, h1.x);
            fma2(aB0, wBa, h0.x);
            fma2(aB1, wBa, h1.x);
            fma2(aA0, wAb, h0.y);
            fma2(aA1, wAb, h1.y);
            fma2(aB0, wBb, h0.y);
            fma2(aB1, wBb, h1.y);
        }

        float2 vA0 = unpack2(aA0), vA1 = unpack2(aA1);
        float2 vB0 = unpack2(aB0), vB1 = unpack2(aB1);
        float gA0 = vA0.x + vA0.y, gA1 = vA1.x + vA1.y;   // col cA, rows 0/1
        float gB0 = vB0.x + vB0.y, gB1 = vB1.x + vB1.y;   // col cB, rows 0/1

        if (half == 1)                            // publish (f_r0, f_r1, o_r0, o_r1)
            fx[u] = make_float4(gA0, gA1, gB0, gB1);
        __syncthreads();                          // barrier 1: f,o partials ready

        if (half == 0) {                          // owns i (gA*) and g (gB*)
            float4 fo = fx[u];
            float* hw = hbuf + ((t + 1) & 1) * 256;
            #pragma unroll
            for (int r = 0; r < 2; r++) {
                float ig = r ? gA1 : gA0;
                float gg = r ? gB1 : gB0;
                float fg = r ? fo.y : fo.x;
                float og = r ? fo.w : fo.z;
                float cn = fmaf(sig_p(fg), cc[r], sig_p(ig) * tanh_p(gg));
                float hn = sig_p(og) * tanh_p(C2LOG2E * cn);
                float ho_, co_;
                if (slot == 0)      { hsA[r] = hn; csA[r] = cn; ho_ = hn; co_ = cn; }
                else if (slot == 1) { hsB[r] = hn; csB[r] = cn; ho_ = hn; co_ = cn; }
                else {
                    ho_ = wt0 * hsA[r] + wt1 * hsB[r] + wt2 * hn;
                    co_ = wt0 * csA[r] + wt1 * csB[r] + wt2 * cn;
                }
                cc[r] = co_;
                hw[r * 128 + u] = ho_;
                (r ? ho1 : ho0)[(size_t)t * HDIM] = ho_;
            }
        }
        slot = (slot == 2) ? 0 : slot + 1;
        __syncthreads();                          // barrier 2: new h published
    }

    // store carried state
    if (half == 0) {
        int parE = (t0 + TSEG) & 1;
        g_hst[si0] = hbuf[parE * 256 + u];
        g_hst[si1] = hbuf[parE * 256 + 128 + u];
        g_cst[si0] = cc[0]; g_cst[si1] = cc[1];
        g_hsA[si0] = hsA[0]; g_hsA[si1] = hsA[1];
        g_hsB[si0] = hsB[0]; g_hsB[si1] = hsB[1];
        g_csA[si0] = csA[0]; g_csA[si1] = csA[1];
        g_csB[si0] = csB[0]; g_csB[si1] = csB[1];
    }
}

// ---------------- kernel 3: logits = hout @ W_br^T + b_br, then log_softmax ----------------
__global__ void __launch_bounds__(256) logits_kernel(const float* __restrict__ W_br,
                                                     const float* __restrict__ b_br,
                                                     float* __restrict__ out) {
    __shared__ float wbr[4 * HDIM];
    __shared__ float bb[4];
    int tid = threadIdx.x;
    for (int i = tid; i < 4 * HDIM; i += 256) wbr[i] = W_br[i];
    if (tid < 4) bb[tid] = b_br[tid];
    __syncthreads();

    int warp = tid >> 5, lane = tid & 31;
    size_t row = (size_t)blockIdx.x * 8 + warp;
    float4 hv = *(const float4*)(g_hout + row * HDIM + lane * 4);

    float p[4];
    #pragma unroll
    for (int o = 0; o < 4; o++) {
        float4 w = *(const float4*)&wbr[o * HDIM + lane * 4];
        p[o] = fmaf(hv.x, w.x, fmaf(hv.y, w.y, fmaf(hv.z, w.z, hv.w * w.w)));
    }
    #pragma unroll
    for (int off = 16; off; off >>= 1) {
        #pragma unroll
        for (int o = 0; o < 4; o++) p[o] += __shfl_xor_sync(0xffffffffu, p[o], off);
    }
    if (lane == 0) {
        float x0 = p[0] + bb[0], x1 = p[1] + bb[1], x2 = p[2] + bb[2], x3 = p[3] + bb[3];
        float m = fmaxf(fmaxf(x0, x1), fmaxf(x2, x3));
        float s = __expf(x0 - m) + __expf(x1 - m) + __expf(x2 - m) + __expf(x3 - m);
        float l = __logf(s);
        *(float4*)(out + row * 4) = make_float4(x0 - m - l, x1 - m - l, x2 - m - l, x3 - m - l);
    }
}

// ---------------- launch ----------------
extern "C" void kernel_launch(void* const* d_in, const int* in_sizes, int n_in,
                              void* d_out, int out_size) {
    const float* x      = (const float*)d_in[0];
    const float* W_in   = (const float*)d_in[1];
    const float* b_in   = (const float*)d_in[2];
    const float* W_ih   = (const float*)d_in[3];
    const float* b_ih   = (const float*)d_in[4];
    const float* W_hh   = (const float*)d_in[5];
    const float* b_hh   = (const float*)d_in[6];
    const float* w_time = (const float*)d_in[7];
    const float* W_br   = (const float*)d_in[8];
    const float* b_br   = (const float*)d_in[9];
    float* out = (float*)d_out;

    combine_kernel<<<GDIM, 128>>>(W_in, b_in, W_ih, b_ih, W_hh, b_hh);
    gemm_kernel<<<dim3(4, 1024), 256>>>(x);

    // hbuf(512f) + fx(128 float4 = 512f) + Wsp(256 * WROW float2)
    size_t shmem = 1024 * sizeof(float) + (size_t)256 * WROW * sizeof(float2);  // 139264 B
    cudaFuncSetAttribute(lstm_kernel, cudaFuncAttributeMaxDynamicSharedMemorySize, (int)shmem);
    for (int s = 0; s < NSEG; s++)
        lstm_kernel<<<BATCH / 2, 256, shmem>>>(w_time, s * TSEG);

    logits_kernel<<<(BATCH * SEQ) / 8, 256>>>(W_br, b_br, out);
}